// round 1
// baseline (speedup 1.0000x reference)
#include <cuda_runtime.h>

// PerturbedTopK:
//   x: (64, 196) f32, noise: (64, 500, 196) f32
//   perturbed = x + SIGMA*noise; per (b,n) row take top-49 indices of 196,
//   sort indices ascending, out[b,k,d] = mean_n [sorted_idx[b,n,k] == d].
//
// Strategy: one warp per row (32000 rows). Each lane holds 7 elements in
// registers. MSB radix-select (with early exit) finds the 49th-largest key;
// then ballot-based ascending-index prefix sums give each selected element
// its rank k directly (no sort). Accumulate with float atomicAdd of the
// constant 1/500 (deterministic: all addends identical).

#define BATCH 64
#define NSAMP 500
#define DIM   196
#define TOPK  49
#define SIGMA 0.05f

#define NROWS (BATCH * NSAMP)
#define OUTN  (BATCH * TOPK * DIM)

__global__ void zero_out_kernel(float* __restrict__ out, int n) {
    int i = blockIdx.x * blockDim.x + threadIdx.x;
    if (i < n) out[i] = 0.0f;
}

__global__ __launch_bounds__(256, 8)
void ptopk_kernel(const float* __restrict__ x,
                  const float* __restrict__ noise,
                  float* __restrict__ out) {
    const int warp = threadIdx.x >> 5;
    const int lane = threadIdx.x & 31;
    const int row  = blockIdx.x * 8 + warp;
    if (row >= NROWS) return;

    const int b = row / NSAMP;
    const float* __restrict__ xr = x + b * DIM;
    const float* __restrict__ nr = noise + (size_t)row * DIM;

    // Load 7 elements per lane (d = j*32 + lane), build order-preserving keys.
    unsigned key[7];
    bool act[7];
    #pragma unroll
    for (int j = 0; j < 7; j++) {
        const int d = j * 32 + lane;
        const bool v = (d < DIM);
        unsigned kk = 0u;
        if (v) {
            const float val = fmaf(nr[d], SIGMA, xr[d]);
            const unsigned u = __float_as_uint(val);
            // monotonic float->uint: pos -> u|0x80000000, neg -> ~u
            kk = u ^ ((unsigned)((int)u >> 31) | 0x80000000u);
        }
        key[j] = kk;
        act[j] = v;          // "active" = still matches current prefix
    }

    // MSB radix select for the TOPK-th largest key.
    // Invariant: 'act' marks keys whose processed high bits == prefix P;
    // 'matching' = |act|; 'k' = how many of the act set still belong to top-K.
    int k = TOPK;
    int matching = DIM;
    unsigned P = 0u;
    int s = 0;                 // lowest processed bit position
    #pragma unroll 1
    for (int bit = 31; bit >= 0; --bit) {
        const unsigned m = 1u << bit;
        int c = 0;
        #pragma unroll
        for (int j = 0; j < 7; j++) c += (act[j] && (key[j] & m)) ? 1 : 0;
        c = __reduce_add_sync(0xffffffffu, c);
        if (c >= k) {
            P |= m;
            matching = c;
            #pragma unroll
            for (int j = 0; j < 7; j++) act[j] = act[j] && (key[j] & m);
        } else {
            k -= c;
            matching -= c;
            #pragma unroll
            for (int j = 0; j < 7; j++) act[j] = act[j] && !(key[j] & m);
        }
        s = bit;
        if (matching == k) break;   // everything still matching is selected
    }

    // Selection + rank by ascending index:
    //   gt  : high bits strictly greater than prefix  -> always selected
    //   eq  : act[] (matches prefix); first 'k' of them by ascending d selected
    //   rank = (#selected with smaller d)
    const unsigned Ph = P >> s;
    const unsigned lt = (1u << lane) - 1u;
    const float invn = 1.0f / (float)NSAMP;
    int gtb = 0, eqb = 0;
    #pragma unroll
    for (int j = 0; j < 7; j++) {
        const int d = j * 32 + lane;
        const bool gt = (d < DIM) && ((key[j] >> s) > Ph);
        const bool eq = act[j];
        const unsigned mg = __ballot_sync(0xffffffffu, gt);
        const unsigned me = __ballot_sync(0xffffffffu, eq);
        const int gtp = gtb + __popc(mg & lt);
        const int eqp = eqb + __popc(me & lt);
        if (gt || (eq && eqp < k)) {
            const int rank = gtp + min(eqp, k);
            atomicAdd(out + ((b * TOPK + rank) * DIM + d), invn);
        }
        gtb += __popc(mg);
        eqb += __popc(me);
    }
}

extern "C" void kernel_launch(void* const* d_in, const int* in_sizes, int n_in,
                              void* d_out, int out_size) {
    // Identify inputs by size for robustness (x: 12544, noise: 6272000).
    const float* x     = (const float*)d_in[0];
    const float* noise = (const float*)d_in[1];
    if (n_in >= 2 && in_sizes[0] > in_sizes[1]) {
        x     = (const float*)d_in[1];
        noise = (const float*)d_in[0];
    }
    float* out = (float*)d_out;

    zero_out_kernel<<<(OUTN + 255) / 256, 256>>>(out, OUTN);
    ptopk_kernel<<<(NROWS + 7) / 8, 256>>>(x, noise, out);
}

// round 2
// speedup vs baseline: 2.9123x; 2.9123x over previous
#include <cuda_runtime.h>

// PerturbedTopK:
//   x: (64, 196) f32, noise: (64, 500, 196) f32
//   perturbed = x + SIGMA*noise; per (b,n) row take top-49 indices of 196,
//   sort indices ascending, out[b,k,d] = mean_n [sorted_idx[b,n,k] == d].
//
// One warp per row (32000 rows), 7 values per lane in registers.
// HOT PATH: value-domain bisection on [0, 1.5] until count(val > piv) == 49
//   exactly (~7 iters, ~22 instrs each). Then selected = {val > piv}: no ties,
//   rank by ascending index via ballot prefix sums, atomicAdd(1/500).
// COLD FALLBACK (bracket miss or duplicate straddling the boundary — never for
//   Gaussian data, but kept for exactness): full MSB radix select with
//   index-order tie-break (the round-1 algorithm), register-lean (keys
//   rematerialized from val, act kept as a 7-bit mask).

#define BATCH 64
#define NSAMP 500
#define DIM   196
#define TOPK  49
#define SIGMA 0.05f

#define NROWS (BATCH * NSAMP)
#define OUTN  (BATCH * TOPK * DIM)
#define FULLM 0xffffffffu

__global__ void zero_out_kernel(float* __restrict__ out, int n) {
    int i = blockIdx.x * blockDim.x + threadIdx.x;
    if (i < n) out[i] = 0.0f;
}

__device__ __forceinline__ unsigned f2key(float v) {
    unsigned u = __float_as_uint(v);
    return u ^ ((unsigned)((int)u >> 31) | 0x80000000u);
}

__global__ __launch_bounds__(256, 8)
void ptopk_kernel(const float* __restrict__ x,
                  const float* __restrict__ noise,
                  float* __restrict__ out) {
    const int warp = threadIdx.x >> 5;
    const int lane = threadIdx.x & 31;
    const int row  = blockIdx.x * 8 + warp;
    if (row >= NROWS) return;

    const int b = row / NSAMP;
    const float* __restrict__ xr = x + b * DIM;
    const float* __restrict__ nr = noise + (size_t)row * DIM;
    const unsigned lt = (1u << lane) - 1u;
    const float invn = 1.0f / (float)NSAMP;
    float* __restrict__ outb = out + b * (TOPK * DIM);

    // Load 7 elements per lane (d = j*32 + lane). Inactive slots -> -FLT_MAX.
    float val[7];
    #pragma unroll
    for (int j = 0; j < 7; j++) {
        const int d = j * 32 + lane;
        val[j] = (d < DIM) ? fmaf(nr[d], SIGMA, xr[d]) : -3.402823466e38f;
    }

    // ---- HOT: bisection for a pivot with count(val > piv) == TOPK ----
    float lo = 0.0f, hi = 1.5f;
    float T = 0.0f;
    bool ok = false;
    #pragma unroll 1
    for (int it = 0; it < 28; ++it) {
        const float piv = 0.5f * (lo + hi);
        int c = 0;
        #pragma unroll
        for (int j = 0; j < 7; j++) c += (val[j] > piv) ? 1 : 0;
        c = __reduce_add_sync(FULLM, c);
        if (c == TOPK) { T = piv; ok = true; break; }
        if (c > TOPK) lo = piv; else hi = piv;
    }

    if (ok) {
        // Exactly TOPK values strictly above T: no tie-breaking needed.
        int base = 0;
        #pragma unroll
        for (int j = 0; j < 7; j++) {
            const int d = j * 32 + lane;
            const bool s = val[j] > T;
            const unsigned mb = __ballot_sync(FULLM, s);
            if (s) {
                const int rank = base + __popc(mb & lt);
                atomicAdd(outb + rank * DIM + d, invn);
            }
            base += __popc(mb);
        }
        return;
    }

    // ---- COLD: exact MSB radix select with index-order tie-break ----
    unsigned actm = (6 * 32 + lane < DIM) ? 0x7Fu : 0x3Fu;
    int k = TOPK;
    int matching = DIM;
    unsigned P = 0u;
    int s = 0;
    #pragma unroll 1
    for (int bit = 31; bit >= 0; --bit) {
        const unsigned m = 1u << bit;
        int c = 0;
        #pragma unroll
        for (int j = 0; j < 7; j++)
            c += (((actm >> j) & 1u) && (f2key(val[j]) & m)) ? 1 : 0;
        c = __reduce_add_sync(FULLM, c);
        if (c >= k) {
            P |= m;
            matching = c;
            #pragma unroll
            for (int j = 0; j < 7; j++)
                if (!(f2key(val[j]) & m)) actm &= ~(1u << j);
        } else {
            k -= c;
            matching -= c;
            #pragma unroll
            for (int j = 0; j < 7; j++)
                if (f2key(val[j]) & m) actm &= ~(1u << j);
        }
        s = bit;
        if (matching == k) break;
    }

    const unsigned Ph = P >> s;
    int gtb = 0, eqb = 0;
    #pragma unroll
    for (int j = 0; j < 7; j++) {
        const int d = j * 32 + lane;
        const bool gt = (d < DIM) && ((f2key(val[j]) >> s) > Ph);
        const bool eq = ((actm >> j) & 1u) != 0u;
        const unsigned mg = __ballot_sync(FULLM, gt);
        const unsigned me = __ballot_sync(FULLM, eq);
        const int gtp = gtb + __popc(mg & lt);
        const int eqp = eqb + __popc(me & lt);
        if (gt || (eq && eqp < k)) {
            const int rank = gtp + min(eqp, k);
            atomicAdd(outb + rank * DIM + d, invn);
        }
        gtb += __popc(mg);
        eqb += __popc(me);
    }
}

extern "C" void kernel_launch(void* const* d_in, const int* in_sizes, int n_in,
                              void* d_out, int out_size) {
    const float* x     = (const float*)d_in[0];
    const float* noise = (const float*)d_in[1];
    if (n_in >= 2 && in_sizes[0] > in_sizes[1]) {
        x     = (const float*)d_in[1];
        noise = (const float*)d_in[0];
    }
    float* out = (float*)d_out;

    zero_out_kernel<<<(OUTN + 255) / 256, 256>>>(out, OUTN);
    ptopk_kernel<<<(NROWS + 7) / 8, 256>>>(x, noise, out);
}